// round 17
// baseline (speedup 1.0000x reference)
#include <cuda_runtime.h>
#include <math.h>

#define HH 256
#define WW 256
#define CC 128
#define BIGF 1000000000.0f

// ---------------- device scratch ----------------
__device__ float g_cost[HH*WW*8];
__device__ float g_dist[2][HH*WW];
__device__ float g_geo [HH*WW];
__device__ float g_var [HH*WW];
__device__ float g_abs2[HH*WW];
__device__ float g_omega[HH*WW];
__device__ unsigned g_arrive;

__device__ __forceinline__ float softplusf(float x){
    return x > 30.0f ? x : log1pf(expf(x));
}

// packed f32x2 helpers (Blackwell SIMD2 fp32: add/mul/fma only)
__device__ __forceinline__ unsigned long long pk2(float x, float y){
    unsigned long long r;
    asm("mov.b64 %0, {%1, %2};" : "=l"(r) : "f"(x), "f"(y));
    return r;
}
__device__ __forceinline__ void fma2(unsigned long long &d, unsigned long long a,
                                     unsigned long long b){
    asm("fma.rn.f32x2 %0, %1, %2, %0;" : "+l"(d) : "l"(a), "l"(b));
}
__device__ __forceinline__ unsigned long long add2(unsigned long long a,
                                                   unsigned long long b){
    unsigned long long r;
    asm("add.rn.f32x2 %0, %1, %2;" : "=l"(r) : "l"(a), "l"(b));
    return r;
}
__device__ __forceinline__ float2 upk2(unsigned long long v){
    float2 r;
    asm("mov.b64 {%0, %1}, %2;" : "=f"(r.x), "=f"(r.y) : "l"(v));
    return r;
}

// ---------------- fused heuristic + cost + MLP + dist BIG-init ----------------
// (R16 version: channel-pair LDS.64 + packed f32x2 stencil math)
// DIRS: 0:(-1,-1) 1:(-1,0) 2:(-1,1) 3:(0,-1) 4:(0,1) 5:(1,-1) 6:(1,0) 7:(1,1)
// cost[p][i] == cost[p+d_i][7-i]; compute i=4..7, mirror-write.
__global__ void hc_k(const float* __restrict__ f, float* __restrict__ out,
                     const float* __restrict__ w1, const float* __restrict__ b1,
                     const float* __restrict__ w2, const float* __restrict__ b2,
                     const int* __restrict__ endn){
    extern __shared__ float dyn[];
    float* sw     = dyn;                       // 4096 floats (W1)
    float* sbuf   = dyn + 4096;                // 2 x (324 cells x 18) = 11664
    float* snorm  = dyn + 4096 + 11664;        // 324
    float* sendlf = snorm + 324;               // 64

    int tid = threadIdx.x;
    int tx = tid & 15, ty = tid >> 4;
    int bh = blockIdx.y*16, bw = blockIdx.x*16;
    int base = (ty+1)*18 + (tx+1);             // cell index

    if (tid == 0 && blockIdx.x == 0 && blockIdx.y == 0) g_arrive = 0u;

    for (int i = tid; i < 1024; i += 256)
        *(float4*)(sw + i*4) = *(const float4*)(w1 + i*4);
    if (tid < 16){
        int e = endn[0]*WW + endn[1];
        *(float4*)(sendlf + tid*4) = *(const float4*)(f + (size_t)e*CC + tid*4);
    }

    for (int idx = tid; idx < 11664; idx += 256) sbuf[idx] = 0.0f;
    __syncthreads();

    int eidx = -1;
    if (tid < 16)      eidx = (tid+2)*18;            // col 0, rows 2..17
    else if (tid < 33) eidx = (tid-15)*18 + 17;      // col 17, rows 1..17
    else if (tid < 49) eidx = 17*18 + (tid-32);      // row 17, cols 1..16

    const unsigned long long PKm1 = pk2(-1.0f,-1.0f);
    const unsigned long long PKp2 = pk2( 2.0f, 2.0f);
    const unsigned long long PKm2 = pk2(-2.0f,-2.0f);
    const unsigned long long PK0  = pk2( 0.0f, 0.0f);

    float geo = 0.0f, var = 0.0f, ab2 = 0.0f;
    unsigned long long own2 = PK0, ep2 = PK0;
    unsigned long long dotp0 = PK0, dotp1 = PK0, dotp2 = PK0, dotp3 = PK0;

    unsigned long long macc[16];
    #pragma unroll
    for (int j=0;j<16;j++) macc[j] = pk2(b1[2*j], b1[2*j+1]);

    auto issue_chunk = [&](int ck, int bsel){
        int c0 = ck*16;
        float* dst = sbuf + bsel*5832;
        for (int idx = tid; idx < 5184; idx += 256){
            int cell = idx >> 4, ch = idx & 15;
            int r = cell / 18, col = cell - r*18;
            int gh = bh + r - 1, gw = bw + col - 1;
            if ((unsigned)gh < HH && (unsigned)gw < WW){
                unsigned sa = (unsigned)__cvta_generic_to_shared(dst + cell*18 + ch);
                asm volatile("cp.async.ca.shared.global [%0], [%1], 4;\n"
                             :: "r"(sa), "l"(f + (size_t)(gh*WW+gw)*CC + c0 + ch));
            }
        }
        asm volatile("cp.async.commit_group;\n");
    };

    issue_chunk(0, 0);

    for (int ck = 0; ck < 8; ck++){
        asm volatile("cp.async.wait_group 0;\n" ::: "memory");
        __syncthreads();
        if (ck < 7) issue_chunk(ck+1, (ck+1)&1);

        const float* sb = sbuf + (ck&1)*5832;
        int c0 = ck*16;

        #pragma unroll
        for (int pr = 0; pr < 8; pr++){
            int chp = 2*pr;
            const float* cb = sb + chp;
            unsigned long long v00 = *(const unsigned long long*)&cb[(base-19)*18];
            unsigned long long v01 = *(const unsigned long long*)&cb[(base-18)*18];
            unsigned long long v02 = *(const unsigned long long*)&cb[(base-17)*18];
            unsigned long long v10 = *(const unsigned long long*)&cb[(base- 1)*18];
            unsigned long long v11 = *(const unsigned long long*)&cb[(base   )*18];
            unsigned long long v12 = *(const unsigned long long*)&cb[(base+ 1)*18];
            unsigned long long v20 = *(const unsigned long long*)&cb[(base+17)*18];
            unsigned long long v21 = *(const unsigned long long*)&cb[(base+18)*18];
            unsigned long long v22 = *(const unsigned long long*)&cb[(base+19)*18];

            // packed Sobel
            unsigned long long gx = v02;
            fma2(gx, v00, PKm1); fma2(gx, v12, PKp2); fma2(gx, v10, PKm2);
            gx = add2(gx, v22);  fma2(gx, v20, PKm1);
            unsigned long long gy = v20;
            fma2(gy, v00, PKm1); fma2(gy, v21, PKp2); fma2(gy, v01, PKm2);
            gy = add2(gy, v22);  fma2(gy, v02, PKm1);
            float2 fgx = upk2(gx), fgy = upk2(gy);
            geo += sqrtf(fgx.x*fgx.x + fgy.x*fgy.x);
            geo += sqrtf(fgx.y*fgx.y + fgy.y*fgy.y);

            // packed norm + cost dots
            fma2(own2,  v11, v11);
            fma2(dotp0, v11, v12);   // (0, 1)
            fma2(dotp1, v11, v20);   // (1,-1)
            fma2(dotp2, v11, v21);   // (1, 0)
            fma2(dotp3, v11, v22);   // (1, 1)

            // MLP layer-1 (broadcast each channel of the pair)
            float2 f11 = upk2(v11);
            {
                unsigned long long fa = pk2(f11.x, f11.x);
                unsigned long long fb = pk2(f11.y, f11.y);
                const ulonglong2* wrA = (const ulonglong2*)(sw + (c0+chp  )*32);
                const ulonglong2* wrB = (const ulonglong2*)(sw + (c0+chp+1)*32);
                #pragma unroll
                for (int q = 0; q < 8; q++){
                    ulonglong2 wv = wrA[q];
                    fma2(macc[2*q  ], fa, wv.x);
                    fma2(macc[2*q+1], fa, wv.y);
                }
                #pragma unroll
                for (int q = 0; q < 8; q++){
                    ulonglong2 wv = wrB[q];
                    fma2(macc[2*q  ], fb, wv.x);
                    fma2(macc[2*q+1], fb, wv.y);
                }
            }

            int c = c0 + chp;
            if (c >= 64){
                unsigned long long xs = add2(v00, v01);
                xs = add2(xs, v02); xs = add2(xs, v10); xs = add2(xs, v11);
                xs = add2(xs, v12); xs = add2(xs, v20); xs = add2(xs, v21);
                xs = add2(xs, v22);
                unsigned long long x2 = PK0;
                fma2(x2, v00, v00); fma2(x2, v01, v01); fma2(x2, v02, v02);
                fma2(x2, v10, v10); fma2(x2, v11, v11); fma2(x2, v12, v12);
                fma2(x2, v20, v20); fma2(x2, v21, v21); fma2(x2, v22, v22);
                float2 fxs = upk2(xs), fx2 = upk2(x2);
                float m1a = fxs.x * (1.0f/9.0f);
                float m1b = fxs.y * (1.0f/9.0f);
                var += fx2.x * (1.0f/9.0f) - m1a*m1a;
                var += fx2.y * (1.0f/9.0f) - m1b*m1b;
            } else {
                float da = f11.x - sendlf[c];
                float db = f11.y - sendlf[c+1];
                ab2 = fmaf(da, da, ab2);
                ab2 = fmaf(db, db, ab2);
            }
        }
        if (tid < 49){
            const float* eb = sb + eidx*18;
            #pragma unroll
            for (int i2 = 0; i2 < 8; i2++){
                unsigned long long e = *(const unsigned long long*)&eb[2*i2];
                fma2(ep2, e, e);
            }
        }
    }

    float ownss;
    float dot4[4];
    {
        float2 t = upk2(own2); ownss = t.x + t.y;
        t = upk2(dotp0); dot4[0] = t.x + t.y;
        t = upk2(dotp1); dot4[1] = t.x + t.y;
        t = upk2(dotp2); dot4[2] = t.x + t.y;
        t = upk2(dotp3); dot4[3] = t.x + t.y;
    }

    int px = (bh+ty)*WW + (bw+tx);
    g_geo [px] = geo * (1.0f/128.0f);
    g_var [px] = var;
    g_abs2[px] = ab2;
    g_dist[0][px] = BIGF;
    g_dist[1][px] = BIGF;

    {
        float z = b2[0];
        #pragma unroll
        for (int j=0;j<16;j++){
            float2 u = upk2(macc[j]);
            z = fmaf(fmaxf(u.x, 0.0f), w2[2*j],   z);
            z = fmaf(fmaxf(u.y, 0.0f), w2[2*j+1], z);
        }
        g_omega[px] = 1.0f / (1.0f + expf(-z));
    }

    __syncthreads();
    snorm[base] = ownss;
    if (tid < 49){
        float2 t = upk2(ep2);
        snorm[eidx] = t.x + t.y;
    }
    __syncthreads();

    int h = bh + ty, w = bw + tx;
    float invp = 1.0f / fmaxf(sqrtf(ownss), 1e-12f);
    const int nbo[4] = {1, 17, 18, 19};
    const int ddx[4] = {0,1,1,1};
    const int ddy[4] = {1,-1,0,1};
    #pragma unroll
    for (int d=0; d<4; d++){
        int i = 4 + d;
        int nh = h + ddx[d], nw = w + ddy[d];
        if ((unsigned)nh < HH && (unsigned)nw < WW){
            float nn = snorm[base + nbo[d]];
            float val = 1.0f - dot4[d] * invp / fmaxf(sqrtf(nn), 1e-12f);
            int npx = nh*WW + nw;
            g_cost[(size_t)px *8 + i]          = val;
            out   [(size_t)px *10 + 1 + i]     = val;
            g_cost[(size_t)npx*8 + (7-i)]      = val;
            out   [(size_t)npx*10 + 1 + (7-i)] = val;
        } else {
            g_cost[(size_t)px*8 + i]      = BIGF;
            out   [(size_t)px*10 + 1 + i] = BIGF;
        }
    }
    const int udx[4] = {-1,-1,-1, 0};
    const int udy[4] = {-1, 0, 1,-1};
    #pragma unroll
    for (int j=0; j<4; j++){
        int nh = h + udx[j], nw = w + udy[j];
        if (!((unsigned)nh < HH && (unsigned)nw < WW)){
            g_cost[(size_t)px*8 + j]      = BIGF;
            out   [(size_t)px*10 + 1 + j] = BIGF;
        }
    }
}

// ---------------- persistent relaxation (R12 verbatim — best measured 122.6us) -
// 256 blocks x 512 threads, occ 2 (barrier overlap). Tile 16x16, halo 8 ->
// region 32x32, 32 phases x K=8. Cheb skip; packed add2 + scalar min tree;
// halo-ring reload; final phase writes output directly.
__global__ void __launch_bounds__(512,2) dist_relax_persist(const int* __restrict__ startn,
                                                            const int* __restrict__ endn,
                                                            const float* __restrict__ dl,
                                                            const float* __restrict__ gm,
                                                            const float* __restrict__ bt,
                                                            float* __restrict__ out){
    __shared__ __align__(16) float sd[2][34][36];
    int tid = threadIdx.x;
    int tx = tid & 15, ty = tid >> 4;     // region row ty (0..31); cells cols 2tx,2tx+1
    int bh = blockIdx.y*16 - 8, bw = blockIdx.x*16 - 8;
    const unsigned NBLK = 256u;

    int sh = startn[0], sw_ = startn[1];
    int d0;
    {
        int rlo = max(bh, 0),  rhi = min(bh+31, HH-1);
        int clo = max(bw, 0),  chi = min(bw+31, WW-1);
        int dr = max(max(rlo - sh, sh - rhi), 0);
        int dc = max(max(clo - sw_, sw_ - chi), 0);
        d0 = max(dr, dc);
    }

    // BIG frame (never written by iterations)
    for (int idx = tid; idx < 2*34*36; idx += 512){
        int l = idx / (34*36);
        int rem = idx % (34*36);
        int r = rem / 36, c = rem % 36;
        if (r == 0 || r == 33 || c == 0 || c >= 33)
            sd[l][r][c] = BIGF;
    }

    unsigned long long cst2[8];
    {
        float ca[8], cb[8];
        int gh = bh + ty;
        int gw0 = bw + 2*tx, gw1 = gw0 + 1;
        bool ok0 = (unsigned)gh < HH && (unsigned)gw0 < WW;
        bool ok1 = (unsigned)gh < HH && (unsigned)gw1 < WW;
        #pragma unroll
        for (int i=0;i<8;i++){ ca[i] = BIGF; cb[i] = BIGF; }
        if (ok0){
            const float4* cp = (const float4*)(g_cost + (size_t)(gh*WW+gw0)*8);
            float4 u = __ldg(cp), w = __ldg(cp+1);
            ca[0]=u.x; ca[1]=u.y; ca[2]=u.z; ca[3]=u.w;
            ca[4]=w.x; ca[5]=w.y; ca[6]=w.z; ca[7]=w.w;
        }
        if (ok1){
            const float4* cp = (const float4*)(g_cost + (size_t)(gh*WW+gw1)*8);
            float4 u = __ldg(cp), w = __ldg(cp+1);
            cb[0]=u.x; cb[1]=u.y; cb[2]=u.z; cb[3]=u.w;
            cb[4]=w.x; cb[5]=w.y; cb[6]=w.z; cb[7]=w.w;
        }
        #pragma unroll
        for (int i=0;i<8;i++) cst2[i] = pk2(ca[i], cb[i]);
    }

    // phase 0 base state in SMEM (BIG except start)
    for (int idx = tid; idx < 1024; idx += 512){
        int r = idx >> 5, c = idx & 31;
        int gh = bh + r, gw = bw + c;
        sd[0][r+1][c+1] = (gh == sh && gw == sw_) ? 0.0f : BIGF;
    }

    #pragma unroll 1
    for (int p = 0; p < 32; p++){
        float* __restrict__ dst = g_dist[(p+1) & 1];
        bool skip = (d0 > 8*(p+1));

        if (!skip){
            if (p > 0){
                const float* __restrict__ src = g_dist[p & 1];
                for (int idx = tid; idx < 768; idx += 512){
                    int r, c;
                    if (idx < 256)      { r = idx >> 5;              c = idx & 31; }
                    else if (idx < 512) { r = 24 + ((idx-256) >> 5); c = idx & 31; }
                    else { int t = idx-512; r = 8 + (t >> 4); int cc = t & 15;
                           c = (cc < 8) ? cc : 16 + cc; }
                    int gh = bh + r, gw = bw + c;
                    float v = BIGF;
                    if ((unsigned)gh < HH && (unsigned)gw < WW)
                        v = __ldcg(src + gh*WW + gw);
                    sd[0][r+1][c+1] = v;
                }
            }
            __syncthreads();

            #pragma unroll
            for (int it = 0; it < 8; it++){
                const int cur = it & 1;
                bool act = (ty >= 1+it) && (ty <= 30-it) &&
                           (2*tx+1 >= 1+it) && (2*tx <= 30-it);
                if (act){
                    unsigned long long a0 = *(const unsigned long long*)&sd[cur][ty  ][2*tx];
                    unsigned long long a1 = *(const unsigned long long*)&sd[cur][ty  ][2*tx+2];
                    unsigned long long b0 = *(const unsigned long long*)&sd[cur][ty+1][2*tx];
                    unsigned long long b1 = *(const unsigned long long*)&sd[cur][ty+1][2*tx+2];
                    unsigned long long c0 = *(const unsigned long long*)&sd[cur][ty+2][2*tx];
                    unsigned long long c1 = *(const unsigned long long*)&sd[cur][ty+2][2*tx+2];

                    float2 fa0 = upk2(a0), fa1 = upk2(a1);
                    float2 fb0 = upk2(b0), fb1 = upk2(b1);
                    float2 fc0 = upk2(c0), fc1 = upk2(c1);

                    unsigned long long mixA = pk2(fa0.y, fa1.x);
                    unsigned long long mixC = pk2(fc0.y, fc1.x);

                    unsigned long long s0 = add2(a0,   cst2[0]);
                    unsigned long long s1 = add2(mixA, cst2[1]);
                    unsigned long long s2 = add2(a1,   cst2[2]);
                    unsigned long long s3 = add2(b0,   cst2[3]);
                    unsigned long long s4 = add2(b1,   cst2[4]);
                    unsigned long long s5 = add2(c0,   cst2[5]);
                    unsigned long long s6 = add2(mixC, cst2[6]);
                    unsigned long long s7 = add2(c1,   cst2[7]);

                    float2 u0 = upk2(s0), u1 = upk2(s1), u2 = upk2(s2), u3 = upk2(s3);
                    float2 u4 = upk2(s4), u5 = upk2(s5), u6 = upk2(s6), u7 = upk2(s7);

                    float v0 = fminf(fb0.y,
                               fminf(fminf(fminf(u0.x,u1.x), fminf(u2.x,u3.x)),
                                     fminf(fminf(u4.x,u5.x), fminf(u6.x,u7.x))));
                    float v1 = fminf(fb1.x,
                               fminf(fminf(fminf(u0.y,u1.y), fminf(u2.y,u3.y)),
                                     fminf(fminf(u4.y,u5.y), fminf(u6.y,u7.y))));

                    sd[cur^1][ty+1][2*tx+1] = v0;
                    sd[cur^1][ty+1][2*tx+2] = v1;
                }
                __syncthreads();
            }
            // 8 iterations (even) -> exact interior in sd[0], rows/cols [8,23]

            if (p < 31){
                if (ty >= 8 && ty < 24 && tx >= 4 && tx < 12){
                    int gh = bh + ty, gw = bw + 2*tx;
                    __stcg(dst + gh*WW + gw,     sd[0][ty+1][2*tx+1]);
                    __stcg(dst + gh*WW + gw + 1, sd[0][ty+1][2*tx+2]);
                }
                __threadfence();
            } else {
                // final phase: write output directly (heuristic + dist)
                if (ty >= 8 && ty < 24 && tx >= 4 && tx < 12){
                    int gh = bh + ty, gw = bw + 2*tx;
                    int e = endn[0]*WW + endn[1];
                    float varEnd = g_var[e];
                    float q0 = softplusf(*dl), q1 = softplusf(*gm), q2 = softplusf(*bt);
                    #pragma unroll
                    for (int b=0; b<2; b++){
                        int px = gh*WW + gw + b;
                        float om = g_omega[px];
                        float hv = q0*g_geo[px]
                                 + om*q1*(varEnd - g_var[px])
                                 + (1.0f - om)*q2*sqrtf(g_abs2[px]);
                        out[(size_t)px*10 + 0] = fmaxf(hv, 0.0f);
                        out[(size_t)px*10 + 9] = fminf(sd[0][ty+1][2*tx+1+b], BIGF);
                    }
                }
            }
        }

        if (p < 31){
            __syncthreads();
            if (tid == 0){
                atomicAdd(&g_arrive, 1u);
                unsigned target = NBLK * (unsigned)(p + 1);
                while (*((volatile unsigned*)&g_arrive) < target) __nanosleep(64);
            }
            __syncthreads();
        }
    }
}

// ---------------- launch ----------------
extern "C" void kernel_launch(void* const* d_in, const int* in_sizes, int n_in,
                              void* d_out, int out_size){
    const float* f = (const float*)d_in[0];
    float* out = (float*)d_out;

    static int smem_set = 0;
    if (!smem_set){
        cudaFuncSetAttribute(hc_k, cudaFuncAttributeMaxDynamicSharedMemorySize, 64592);
        smem_set = 1;
    }

    hc_k<<<dim3(16,16), 256, 64592>>>(f, out, (const float*)d_in[4], (const float*)d_in[5],
                                      (const float*)d_in[6], (const float*)d_in[7],
                                      (const int*)d_in[9]);
    dist_relax_persist<<<dim3(16,16), 512>>>((const int*)d_in[8], (const int*)d_in[9],
                                             (const float*)d_in[1], (const float*)d_in[2],
                                             (const float*)d_in[3], out);
}